// round 5
// baseline (speedup 1.0000x reference)
#include <cuda_runtime.h>
#include <math.h>

#define FEAT  52
#define NPIX  2704
#define NA    24336
#define PRE   12000
#define POST  2000
#define NCB   188

#define OUT_ROIS 0
#define OUT_LOCS 8000
#define OUT_CLS1 105344
#define OUT_OBJ  154016
#define OUT_CLS2 178352

#define SMEM_CONV ((256*3*54 + 128*32) * 4)

// ---------------- device scratch (static, no allocs) ----------------
__device__ float  g_wt[2304 * 256];           // [(kh*3+kw)*256+ci][co]
__device__ float4 g_h4[NPIX * 64];            // conv1 output, [p][256]
__device__ float4 g_roi4[NA];
__device__ unsigned char g_valid[NA];
__device__ unsigned long long g_key[NA + 64];  // +pad for vector loads
__device__ float4 g_sbox[PRE];
__device__ float  g_sarea[PRE];
__device__ unsigned long long g_mask[(size_t)PRE * NCB];
__device__ unsigned long long g_rem0[NCB];

// ---------------- Cephes/Eigen-style expf (matches XLA CPU vectorized exp) --
__device__ __forceinline__ float cephes_expf(float x) {
    float m = floorf(fmaf(x, 1.44269504088896341f, 0.5f));
    float r = fmaf(m, -0.693359375f, x);
    r = fmaf(m, 2.12194440e-4f, r);
    float r2 = __fmul_rn(r, r);
    float y = 1.9875691500E-4f;
    y = fmaf(y, r, 1.3981999507E-3f);
    y = fmaf(y, r, 8.3334519073E-3f);
    y = fmaf(y, r, 4.1665795894E-2f);
    y = fmaf(y, r, 1.6666665459E-1f);
    y = fmaf(y, r, 5.0000001201E-1f);
    y = fmaf(y, r2, r);
    y = __fadd_rn(y, 1.0f);
    return ldexpf(y, (int)m);
}

// ---------------- 1: weight transpose + output/scratch zeroing -------------
__global__ void k_wt(const float* __restrict__ w, float* __restrict__ out) {
    int o = blockIdx.x * 256 + threadIdx.x;
    if (o < 2304 * 256) {
        int co  = o & 255;
        int k   = o >> 8;
        int ci  = k & 255;
        int khw = k >> 8;
        g_wt[o] = w[co * 2304 + ci * 9 + khw];
    }
    if (o < 8000) out[OUT_ROIS + o] = 0.f;
    if (o < NCB)  g_rem0[o] = 0ull;
}

// ---------------- 2: conv1 3x3 SAME 256->256, strict (kh,kw,ci) FMA chain --
// grid (8 cog, 52 y), 208 threads: quad = t&15 (2 co each), pxg = t>>4 (4 px)
__global__ __launch_bounds__(208) void k_conv(const float* __restrict__ x,
                                              const float* __restrict__ bias) {
    extern __shared__ float smem[];
    float* s_in = smem;                       // [ci*3+row][54]
    float* s_w  = smem + 256 * 3 * 54;        // [ci_local][32co]
    int t = threadIdx.x;
    int cog = blockIdx.x, y = blockIdx.y;
    int quad = t & 15;
    int pxg  = t >> 4;

    float acc[2][4];
#pragma unroll
    for (int c = 0; c < 2; c++)
#pragma unroll
        for (int j = 0; j < 4; j++) acc[c][j] = 0.f;

    for (int e = t; e < 256 * 3 * 54; e += 208) {
        int ci  = e / 162;
        int rem = e - ci * 162;
        int row = rem / 54;
        int col = rem - row * 54;
        int yy = y + row - 1;
        int xx = col - 1;
        float v = 0.f;
        if ((unsigned)yy < 52u && (unsigned)xx < 52u)
            v = x[ci * NPIX + yy * 52 + xx];
        s_in[e] = v;
    }

    for (int khw = 0; khw < 9; khw++) {
        int kh = khw / 3, kw = khw - 3 * (khw / 3);
        for (int half = 0; half < 2; half++) {
            __syncthreads();
            for (int e = t; e < 4096; e += 208)
                s_w[e] = g_wt[((khw << 8) + (half << 7) + (e >> 5)) * 256 + cog * 32 + (e & 31)];
            __syncthreads();
            int inbase = (half * 128) * 162 + kh * 54 + pxg * 4 + kw;
#pragma unroll 4
            for (int ci = 0; ci < 128; ci++) {
                const float* ip = &s_in[inbase + ci * 162];
                float v0 = ip[0], v1 = ip[1], v2 = ip[2], v3 = ip[3];
                const float2 wv = *(const float2*)&s_w[ci * 32 + quad * 2];
                acc[0][0] = fmaf(wv.x, v0, acc[0][0]);
                acc[0][1] = fmaf(wv.x, v1, acc[0][1]);
                acc[0][2] = fmaf(wv.x, v2, acc[0][2]);
                acc[0][3] = fmaf(wv.x, v3, acc[0][3]);
                acc[1][0] = fmaf(wv.y, v0, acc[1][0]);
                acc[1][1] = fmaf(wv.y, v1, acc[1][1]);
                acc[1][2] = fmaf(wv.y, v2, acc[1][2]);
                acc[1][3] = fmaf(wv.y, v3, acc[1][3]);
            }
        }
    }

    float* h = (float*)g_h4;
#pragma unroll
    for (int c = 0; c < 2; c++) {
        int co = cog * 32 + quad * 2 + c;
        float b = bias[co];
#pragma unroll
        for (int j = 0; j < 4; j++) {
            int px = pxg * 4 + j;
            h[(y * 52 + px) * 256 + co] = __fadd_rn(acc[c][j], b);
        }
    }
}

// ---------------- 3: fused 1x1 heads + anchor decode + sort-key build ------
// 216 threads: px = t/54 (4 px per block), o = t%54 (0..35 reg, 36..53 cls)
__global__ __launch_bounds__(216) void k_heads(const float* __restrict__ rw,
                                               const float* __restrict__ rb,
                                               const float* __restrict__ cw,
                                               const float* __restrict__ cbp,
                                               float* __restrict__ out) {
    __shared__ float s_h[4 * 256];
    __shared__ float s_w[54 * 129];
    __shared__ float s_res[4][56];
    int t = threadIdx.x;
    int pxb = blockIdx.x * 4;
    const float* h = (const float*)g_h4;
    for (int e = t; e < 1024; e += 216)
        s_h[e] = h[(size_t)pxb * 256 + e];

    int px = t / 54;
    int o  = t - px * 54;
    float acc = 0.f;
    for (int hs = 0; hs < 2; hs++) {
        __syncthreads();
        for (int e = t; e < 54 * 128; e += 216) {
            int oo = e >> 7, ci = e & 127;
            float wv = (oo < 36) ? rw[oo * 256 + hs * 128 + ci]
                                 : cw[(oo - 36) * 256 + hs * 128 + ci];
            s_w[oo * 129 + ci] = wv;
        }
        __syncthreads();
        const float* hp = &s_h[px * 256 + hs * 128];
        const float* wp = &s_w[o * 129];
#pragma unroll 8
        for (int ci = 0; ci < 128; ci++)
            acc = fmaf(wp[ci], hp[ci], acc);
    }
    int pg = pxb + px;
    float resv;
    if (o < 36) {
        resv = __fadd_rn(acc, __ldg(rb + o));
        out[OUT_LOCS + pg * 36 + o] = resv;
    } else {
        int oc = o - 36;
        resv = __fadd_rn(acc, __ldg(cbp + oc));
        out[OUT_CLS1 + pg * 18 + oc] = resv;
        out[OUT_CLS2 + pg * 18 + oc] = resv;
        if (oc & 1) out[OUT_OBJ + pg * 9 + (oc >> 1)] = resv;
    }
    s_res[px][o] = resv;
    __syncthreads();

    // fused decode: 36 threads = 4 px x 9 anchors
    if (t < 36) {
        int px2 = t / 9, a = t - px2 * 9;
        int pg2 = pxb + px2;
        int i = pg2 * 9 + a;
        int ri = a / 3, si = a - ri * 3;
        double ratio = (ri == 0) ? 0.5 : (ri == 1 ? 1.0 : 2.0);
        double scale = (si == 0) ? 4.0 : (si == 1 ? 8.0 : 16.0);
        double hd = 4.0 * scale * sqrt(ratio);
        double wd = 4.0 * scale * sqrt(1.0 / ratio);
        double cyd = (double)(4 * (pg2 / 52) + 2);
        double cxd = (double)(4 * (pg2 % 52) + 2);
        float a0 = (float)(cyd - hd * 0.5);
        float a1 = (float)(cxd - wd * 0.5);
        float a2 = (float)(cyd + hd * 0.5);
        float a3 = (float)(cxd + wd * 0.5);

        float ah = __fsub_rn(a2, a0), aw = __fsub_rn(a3, a1);
        float acy = __fadd_rn(a0, __fmul_rn(0.5f, ah));
        float acx = __fadd_rn(a1, __fmul_rn(0.5f, aw));

        float l0 = s_res[px2][a * 4 + 0];
        float l1 = s_res[px2][a * 4 + 1];
        float l2 = s_res[px2][a * 4 + 2];
        float l3 = s_res[px2][a * 4 + 3];
        float s  = s_res[px2][36 + a * 2 + 1];

        float cy = __fadd_rn(__fmul_rn(l0, ah), acy);
        float cx = __fadd_rn(__fmul_rn(l1, aw), acx);
        float hh = __fmul_rn(cephes_expf(l2), ah);
        float ww = __fmul_rn(cephes_expf(l3), aw);
        float r0 = __fsub_rn(cy, __fmul_rn(0.5f, hh));
        float r1 = __fsub_rn(cx, __fmul_rn(0.5f, ww));
        float r2 = __fadd_rn(cy, __fmul_rn(0.5f, hh));
        float r3 = __fadd_rn(cx, __fmul_rn(0.5f, ww));
        r0 = fminf(fmaxf(r0, 0.f), 210.f);
        r1 = fminf(fmaxf(r1, 0.f), 210.f);
        r2 = fminf(fmaxf(r2, 0.f), 210.f);
        r3 = fminf(fmaxf(r3, 0.f), 210.f);
        float hs = __fsub_rn(r2, r0), ws = __fsub_rn(r3, r1);
        bool valid = (hs >= 16.f) && (ws >= 16.f);

        g_roi4[i] = make_float4(r0, r1, r2, r3);
        g_valid[i] = valid ? 1 : 0;

        float sm = valid ? s : __int_as_float(0xff800000);
        unsigned u = __float_as_uint(sm);
        u = (u & 0x80000000u) ? ~u : (u | 0x80000000u);
        g_key[i] = ((unsigned long long)(~u) << 32) | (unsigned long long)(unsigned)i;
    }
}

// ---------------- 4: brute-force stable rank (replaces sort + gather) ------
// rank(i) = #{j : key_j < key_i}; keys unique -> exact stable argsort.
__global__ __launch_bounds__(256) void k_rank() {
    __shared__ ulonglong2 sk2[1024];            // 2048 keys per chunk
    int i = blockIdx.x * 256 + threadIdx.x;     // 96 blocks -> 24576 >= NA
    unsigned long long my = (i < NA) ? g_key[i] : 0ull;
    int rank = 0;
    for (int chunk = 0; chunk < 12; chunk++) {
        int base = chunk * 2048;
        __syncthreads();
        for (int e = threadIdx.x; e < 1024; e += 256) {
            int g0 = base + 2 * e;
            ulonglong2 v;
            v.x = (g0     < NA) ? g_key[g0]     : ~0ull;
            v.y = (g0 + 1 < NA) ? g_key[g0 + 1] : ~0ull;
            sk2[e] = v;
        }
        __syncthreads();
#pragma unroll 8
        for (int j = 0; j < 1024; j++) {
            ulonglong2 v = sk2[j];
            rank += (v.x < my);
            rank += (v.y < my);
        }
    }
    if (i < NA && rank < PRE) {
        float4 b = g_roi4[i];
        g_sbox[rank] = b;
        g_sarea[rank] = __fmul_rn(__fadd_rn(__fsub_rn(b.w, b.y), 1.f),
                                  __fadd_rn(__fsub_rn(b.z, b.x), 1.f));
        if (!g_valid[i]) atomicOr(&g_rem0[rank >> 6], 1ull << (rank & 63));
    }
}

// ---------------- 5: IoU suppression-mask matrix (upper triangle) ----------
__global__ __launch_bounds__(256) void k_mask() {
    int cc = blockIdx.x;
    int rc = blockIdx.y * 4 + (threadIdx.x >> 6);
    int t  = threadIdx.x & 63;
    __shared__ float4 cb[64];
    __shared__ float  ca[64];
    if (threadIdx.x < 64) {
        int jg = cc * 64 + threadIdx.x;
        if (jg < PRE) { cb[threadIdx.x] = g_sbox[jg]; ca[threadIdx.x] = g_sarea[jg]; }
        else          { cb[threadIdx.x] = make_float4(0.f, 0.f, 0.f, 0.f); ca[threadIdx.x] = 0.f; }
    }
    __syncthreads();
    if (cc < rc) return;
    int ig = rc * 64 + t;
    if (ig >= PRE) return;
    float4 b = g_sbox[ig];
    float ai = g_sarea[ig];
    unsigned long long bits = 0ull;
    int jmax = min(64, PRE - cc * 64);
    for (int j = 0; j < jmax; j++) {
        int jj = cc * 64 + j;
        if (jj <= ig) continue;
        float4 c = cb[j];
        float yy1 = fmaxf(b.x, c.x), xx1 = fmaxf(b.y, c.y);
        float yy2 = fminf(b.z, c.z), xx2 = fminf(b.w, c.w);
        float dx = __fadd_rn(__fsub_rn(xx2, xx1), 1.f);
        float dy = __fadd_rn(__fsub_rn(yy2, yy1), 1.f);
        float inter = __fmul_rn(fmaxf(0.f, dx), fmaxf(0.f, dy));
        float denom = __fsub_rn(__fadd_rn(ai, ca[j]), inter);
        float diff = __fsub_rn(inter, __fmul_rn(0.7f, denom));
        bool gt;
        if (fabsf(diff) > 1e-5f * denom)
            gt = (diff > 0.f);
        else
            gt = (__fdiv_rn(inter, denom) > 0.7f);
        if (gt) bits |= (1ull << j);
    }
    g_mask[(size_t)ig * NCB + cc] = bits;
}

// ---------------- 6: chunked greedy NMS + ROI write ------------------------
__global__ __launch_bounds__(256) void k_nms(float* __restrict__ out) {
    __shared__ unsigned long long remv[NCB];
    __shared__ unsigned long long sdiag[2][64];
    __shared__ unsigned long long s_kept;
    __shared__ int s_base, s_stop;
    int t = threadIdx.x;
    if (t < NCB) remv[t] = g_rem0[t];
    if (t == 0) { s_base = 0; s_stop = 0; }
    if (t < 64) sdiag[0][t] = g_mask[(size_t)t * NCB + 0];   // chunk 0 diag (rows<PRE)
    __syncthreads();
    for (int c = 0; c < NCB; c++) {
        int buf = c & 1;
        // prefetch next diagonal with warps 2-3 while t==0 resolves
        if (t >= 64 && t < 128 && c + 1 < NCB) {
            int row = (c + 1) * 64 + (t - 64);
            sdiag[1 - buf][t - 64] = (row < PRE) ? g_mask[(size_t)row * NCB + (c + 1)] : 0ull;
        }
        if (t == 0) {
            unsigned long long sup = remv[c];
            if (c == NCB - 1) sup |= ~((1ull << 32) - 1ull);   // rows >= PRE (12000%64==32)
            unsigned long long kept = 0ull;
            unsigned long long avail = ~sup;
            while (avail) {
                int i = __ffsll((long long)avail) - 1;
                kept |= (1ull << i);
                sup |= sdiag[buf][i];
                unsigned long long lowmask = (i == 63) ? ~0ull : ((2ull << i) - 1ull);
                avail = avail & ~sup & ~lowmask;
            }
            s_kept = kept;
        }
        __syncthreads();
        unsigned long long kept = s_kept;
        int base = s_base;
        if (t < 64 && ((kept >> t) & 1ull)) {
            int pos = base + __popcll(kept & ((1ull << t) - 1ull));
            if (pos < POST) {
                float4 b = g_sbox[c * 64 + t];
                out[OUT_ROIS + pos * 4 + 0] = b.x;
                out[OUT_ROIS + pos * 4 + 1] = b.y;
                out[OUT_ROIS + pos * 4 + 2] = b.z;
                out[OUT_ROIS + pos * 4 + 3] = b.w;
            }
        }
        if (t > c && t < NCB) {
            unsigned long long acc = remv[t];
            unsigned long long k2 = kept;
            while (k2) {
                int i = __ffsll((long long)k2) - 1;
                k2 &= (k2 - 1ull);
                acc |= g_mask[(size_t)(c * 64 + i) * NCB + t];
            }
            remv[t] = acc;
        }
        if (t == 0) {
            s_base = base + __popcll(kept);
            s_stop = (s_base >= POST) ? 1 : 0;
        }
        __syncthreads();
        if (s_stop) return;
    }
}

// ---------------- launch ----------------------------------------------------
extern "C" void kernel_launch(void* const* d_in, const int* in_sizes, int n_in,
                              void* d_out, int out_size) {
    const float* x   = (const float*)d_in[0];
    const float* c1w = (const float*)d_in[1];
    const float* c1b = (const float*)d_in[2];
    const float* rw  = (const float*)d_in[3];
    const float* rb  = (const float*)d_in[4];
    const float* cw  = (const float*)d_in[5];
    const float* cb  = (const float*)d_in[6];
    float* out = (float*)d_out;

    cudaFuncSetAttribute(k_conv, cudaFuncAttributeMaxDynamicSharedMemorySize, SMEM_CONV);

    k_wt<<<2304, 256>>>(c1w, out);
    k_conv<<<dim3(8, 52), 208, SMEM_CONV>>>(x, c1b);
    k_heads<<<676, 216>>>(rw, rb, cw, cb, out);
    k_rank<<<96, 256>>>();
    k_mask<<<dim3(NCB, 47), 256>>>();
    k_nms<<<1, 256>>>(out);
}

// round 6
// speedup vs baseline: 2.0569x; 2.0569x over previous
#include <cuda_runtime.h>
#include <cooperative_groups.h>
#include <math.h>

namespace cg = cooperative_groups;

#define FEAT  52
#define NPIX  2704
#define NA    24336
#define NSORT 32768
#define PRE   12000
#define POST  2000
#define NCB   188

#define OUT_ROIS 0
#define OUT_LOCS 8000
#define OUT_CLS1 105344
#define OUT_OBJ  154016
#define OUT_CLS2 178352

#define SMEM_CONV ((256*3*54 + 128*64) * 4)

// ---------------- device scratch (static, no allocs) ----------------
__device__ float  g_wt[2304 * 256];           // [(kh*3+kw)*256+ci][co]
__device__ float4 g_h4[NPIX * 64];            // conv1 output, [p][256]
__device__ float4 g_roi4[NA];
__device__ unsigned char g_valid[NA];
__device__ unsigned long long g_key[NSORT];
__device__ float4 g_sbox[PRE];
__device__ float  g_sarea[PRE];
__device__ unsigned long long g_rem0[NCB];
// cooperative-NMS state
__device__ float4 g_kept_box[2304];
__device__ float  g_kept_area[2304];
__device__ int    g_nkept;
__device__ int    g_done;
__device__ unsigned long long g_csup[4];
__device__ unsigned long long g_gdiag[256 * 4];   // [i*4+w]

// ---------------- Cephes/Eigen-style expf ----------------------------------
__device__ __forceinline__ float cephes_expf(float x) {
    float m = floorf(fmaf(x, 1.44269504088896341f, 0.5f));
    float r = fmaf(m, -0.693359375f, x);
    r = fmaf(m, 2.12194440e-4f, r);
    float r2 = __fmul_rn(r, r);
    float y = 1.9875691500E-4f;
    y = fmaf(y, r, 1.3981999507E-3f);
    y = fmaf(y, r, 8.3334519073E-3f);
    y = fmaf(y, r, 4.1665795894E-2f);
    y = fmaf(y, r, 1.6666665459E-1f);
    y = fmaf(y, r, 5.0000001201E-1f);
    y = fmaf(y, r2, r);
    y = __fadd_rn(y, 1.0f);
    return ldexpf(y, (int)m);
}

// exact IoU>0.7 test (fast path + bit-exact div fallback in ambiguous band)
__device__ __forceinline__ bool iou_gt(float4 b, float ai, float4 c, float aj) {
    float yy1 = fmaxf(b.x, c.x), xx1 = fmaxf(b.y, c.y);
    float yy2 = fminf(b.z, c.z), xx2 = fminf(b.w, c.w);
    float dx = __fadd_rn(__fsub_rn(xx2, xx1), 1.f);
    float dy = __fadd_rn(__fsub_rn(yy2, yy1), 1.f);
    float inter = __fmul_rn(fmaxf(0.f, dx), fmaxf(0.f, dy));
    float denom = __fsub_rn(__fadd_rn(ai, aj), inter);
    float diff = __fsub_rn(inter, __fmul_rn(0.7f, denom));
    if (fabsf(diff) > 1e-5f * denom) return diff > 0.f;
    return __fdiv_rn(inter, denom) > 0.7f;
}

// ---------------- 1: weight transpose + zeroing + state init ---------------
__global__ void k_wt(const float* __restrict__ w, float* __restrict__ out) {
    int o = blockIdx.x * 256 + threadIdx.x;
    if (o < 2304 * 256) {
        int co  = o & 255;
        int k   = o >> 8;
        int ci  = k & 255;
        int khw = k >> 8;
        g_wt[o] = w[co * 2304 + ci * 9 + khw];
    }
    if (o < 8000) out[OUT_ROIS + o] = 0.f;
    if (o < NCB)  g_rem0[o] = 0ull;
    if (o < NSORT - NA) g_key[NA + o] = ~0ull;   // sort padding
    if (o == 0) { g_nkept = 0; g_done = 0; }
    if (o < 4) g_csup[o] = 0ull;
}

// ---------------- 2: conv1 3x3 SAME 256->256, strict (kh,kw,ci) FMA chain --
// grid (4 cog, 52 y), 208 threads: quad = t&15 (4 co), pxg = t>>4 (4 px)
__global__ __launch_bounds__(208) void k_conv(const float* __restrict__ x,
                                              const float* __restrict__ bias) {
    extern __shared__ float smem[];
    float* s_in = smem;                       // [ci*3+row][54]
    float* s_w  = smem + 256 * 3 * 54;        // [ci_local][64co]
    int t = threadIdx.x;
    int cog = blockIdx.x, y = blockIdx.y;
    int quad = t & 15;
    int pxg  = t >> 4;

    float acc[4][4];
#pragma unroll
    for (int c = 0; c < 4; c++)
#pragma unroll
        for (int j = 0; j < 4; j++) acc[c][j] = 0.f;

    for (int e = t; e < 256 * 3 * 54; e += 208) {
        int ci  = e / 162;
        int rem = e - ci * 162;
        int row = rem / 54;
        int col = rem - row * 54;
        int yy = y + row - 1;
        int xx = col - 1;
        float v = 0.f;
        if ((unsigned)yy < 52u && (unsigned)xx < 52u)
            v = x[ci * NPIX + yy * 52 + xx];
        s_in[e] = v;
    }

    for (int khw = 0; khw < 9; khw++) {
        int kh = khw / 3, kw = khw - 3 * (khw / 3);
        for (int half = 0; half < 2; half++) {
            __syncthreads();
            for (int e = t; e < 8192; e += 208)
                s_w[e] = g_wt[((khw << 8) + (half << 7) + (e >> 6)) * 256 + cog * 64 + (e & 63)];
            __syncthreads();
            int inbase = (half * 128) * 162 + kh * 54 + pxg * 4 + kw;
#pragma unroll 4
            for (int ci = 0; ci < 128; ci++) {
                const float* ip = &s_in[inbase + ci * 162];
                float v0 = ip[0], v1 = ip[1], v2 = ip[2], v3 = ip[3];
                const float4 wv = *(const float4*)&s_w[ci * 64 + quad * 4];
                acc[0][0] = fmaf(wv.x, v0, acc[0][0]);
                acc[0][1] = fmaf(wv.x, v1, acc[0][1]);
                acc[0][2] = fmaf(wv.x, v2, acc[0][2]);
                acc[0][3] = fmaf(wv.x, v3, acc[0][3]);
                acc[1][0] = fmaf(wv.y, v0, acc[1][0]);
                acc[1][1] = fmaf(wv.y, v1, acc[1][1]);
                acc[1][2] = fmaf(wv.y, v2, acc[1][2]);
                acc[1][3] = fmaf(wv.y, v3, acc[1][3]);
                acc[2][0] = fmaf(wv.z, v0, acc[2][0]);
                acc[2][1] = fmaf(wv.z, v1, acc[2][1]);
                acc[2][2] = fmaf(wv.z, v2, acc[2][2]);
                acc[2][3] = fmaf(wv.z, v3, acc[2][3]);
                acc[3][0] = fmaf(wv.w, v0, acc[3][0]);
                acc[3][1] = fmaf(wv.w, v1, acc[3][1]);
                acc[3][2] = fmaf(wv.w, v2, acc[3][2]);
                acc[3][3] = fmaf(wv.w, v3, acc[3][3]);
            }
        }
    }

    float* h = (float*)g_h4;
#pragma unroll
    for (int c = 0; c < 4; c++) {
        int co = cog * 64 + quad * 4 + c;
        float b = bias[co];
#pragma unroll
        for (int j = 0; j < 4; j++) {
            int px = pxg * 4 + j;
            h[(y * 52 + px) * 256 + co] = __fadd_rn(acc[c][j], b);
        }
    }
}

// ---------------- 3: fused 1x1 heads + anchor decode + sort-key build ------
__global__ __launch_bounds__(216) void k_heads(const float* __restrict__ rw,
                                               const float* __restrict__ rb,
                                               const float* __restrict__ cw,
                                               const float* __restrict__ cbp,
                                               float* __restrict__ out) {
    __shared__ float s_h[4 * 256];
    __shared__ float s_w[54 * 129];
    __shared__ float s_res[4][56];
    int t = threadIdx.x;
    int pxb = blockIdx.x * 4;
    const float* h = (const float*)g_h4;
    for (int e = t; e < 1024; e += 216)
        s_h[e] = h[(size_t)pxb * 256 + e];

    int px = t / 54;
    int o  = t - px * 54;
    float acc = 0.f;
    for (int hs = 0; hs < 2; hs++) {
        __syncthreads();
        for (int e = t; e < 54 * 128; e += 216) {
            int oo = e >> 7, ci = e & 127;
            float wv = (oo < 36) ? rw[oo * 256 + hs * 128 + ci]
                                 : cw[(oo - 36) * 256 + hs * 128 + ci];
            s_w[oo * 129 + ci] = wv;
        }
        __syncthreads();
        const float* hp = &s_h[px * 256 + hs * 128];
        const float* wp = &s_w[o * 129];
#pragma unroll 8
        for (int ci = 0; ci < 128; ci++)
            acc = fmaf(wp[ci], hp[ci], acc);
    }
    int pg = pxb + px;
    float resv;
    if (o < 36) {
        resv = __fadd_rn(acc, __ldg(rb + o));
        out[OUT_LOCS + pg * 36 + o] = resv;
    } else {
        int oc = o - 36;
        resv = __fadd_rn(acc, __ldg(cbp + oc));
        out[OUT_CLS1 + pg * 18 + oc] = resv;
        out[OUT_CLS2 + pg * 18 + oc] = resv;
        if (oc & 1) out[OUT_OBJ + pg * 9 + (oc >> 1)] = resv;
    }
    s_res[px][o] = resv;
    __syncthreads();

    if (t < 36) {
        int px2 = t / 9, a = t - px2 * 9;
        int pg2 = pxb + px2;
        int i = pg2 * 9 + a;
        int ri = a / 3, si = a - ri * 3;
        double ratio = (ri == 0) ? 0.5 : (ri == 1 ? 1.0 : 2.0);
        double scale = (si == 0) ? 4.0 : (si == 1 ? 8.0 : 16.0);
        double hd = 4.0 * scale * sqrt(ratio);
        double wd = 4.0 * scale * sqrt(1.0 / ratio);
        double cyd = (double)(4 * (pg2 / 52) + 2);
        double cxd = (double)(4 * (pg2 % 52) + 2);
        float a0 = (float)(cyd - hd * 0.5);
        float a1 = (float)(cxd - wd * 0.5);
        float a2 = (float)(cyd + hd * 0.5);
        float a3 = (float)(cxd + wd * 0.5);

        float ah = __fsub_rn(a2, a0), aw = __fsub_rn(a3, a1);
        float acy = __fadd_rn(a0, __fmul_rn(0.5f, ah));
        float acx = __fadd_rn(a1, __fmul_rn(0.5f, aw));

        float l0 = s_res[px2][a * 4 + 0];
        float l1 = s_res[px2][a * 4 + 1];
        float l2 = s_res[px2][a * 4 + 2];
        float l3 = s_res[px2][a * 4 + 3];
        float s  = s_res[px2][36 + a * 2 + 1];

        float cy = __fadd_rn(__fmul_rn(l0, ah), acy);
        float cx = __fadd_rn(__fmul_rn(l1, aw), acx);
        float hh = __fmul_rn(cephes_expf(l2), ah);
        float ww = __fmul_rn(cephes_expf(l3), aw);
        float r0 = __fsub_rn(cy, __fmul_rn(0.5f, hh));
        float r1 = __fsub_rn(cx, __fmul_rn(0.5f, ww));
        float r2 = __fadd_rn(cy, __fmul_rn(0.5f, hh));
        float r3 = __fadd_rn(cx, __fmul_rn(0.5f, ww));
        r0 = fminf(fmaxf(r0, 0.f), 210.f);
        r1 = fminf(fmaxf(r1, 0.f), 210.f);
        r2 = fminf(fmaxf(r2, 0.f), 210.f);
        r3 = fminf(fmaxf(r3, 0.f), 210.f);
        float hs = __fsub_rn(r2, r0), ws = __fsub_rn(r3, r1);
        bool valid = (hs >= 16.f) && (ws >= 16.f);

        g_roi4[i] = make_float4(r0, r1, r2, r3);
        g_valid[i] = valid ? 1 : 0;

        float sm = valid ? s : __int_as_float(0xff800000);
        unsigned u = __float_as_uint(sm);
        u = (u & 0x80000000u) ? ~u : (u | 0x80000000u);
        g_key[i] = ((unsigned long long)(~u) << 32) | (unsigned long long)(unsigned)i;
    }
}

// ---------------- 4: bitonic sort (32768 keys ascending) -------------------
__device__ __forceinline__ void cswap(unsigned long long& a, unsigned long long& b, bool asc) {
    bool sw = asc ? (a > b) : (a < b);
    if (sw) { unsigned long long tt = a; a = b; b = tt; }
}

__device__ void bitonic_tile(unsigned long long* sk, int base, int t, int s, int jmax) {
    for (int j = jmax; j >= 1; j >>= 1) {
        __syncthreads();
#pragma unroll
        for (int q = 0; q < 2; q++) {
            int p = t + q * 1024;
            int i = 2 * p - (p & (j - 1));
            bool asc = (((base + i) & s) == 0);
            unsigned long long a = sk[i], b = sk[i + j];
            cswap(a, b, asc);
            sk[i] = a; sk[i + j] = b;
        }
    }
}

__global__ __launch_bounds__(1024) void k_sort_local_full() {
    __shared__ unsigned long long sk[4096];
    int t = threadIdx.x, base = blockIdx.x * 4096;
#pragma unroll
    for (int q = 0; q < 4; q++) sk[t + q * 1024] = g_key[base + t + q * 1024];
    for (int s = 2; s <= 4096; s <<= 1) bitonic_tile(sk, base, t, s, s >> 1);
    __syncthreads();
#pragma unroll
    for (int q = 0; q < 4; q++) g_key[base + t + q * 1024] = sk[t + q * 1024];
}

__global__ __launch_bounds__(1024) void k_sort_local_tail(int s) {
    __shared__ unsigned long long sk[4096];
    int t = threadIdx.x, base = blockIdx.x * 4096;
#pragma unroll
    for (int q = 0; q < 4; q++) sk[t + q * 1024] = g_key[base + t + q * 1024];
    bitonic_tile(sk, base, t, s, 2048);
    __syncthreads();
#pragma unroll
    for (int q = 0; q < 4; q++) g_key[base + t + q * 1024] = sk[t + q * 1024];
}

__global__ void k_sort_global(int j, int s) {
    int p = blockIdx.x * 256 + threadIdx.x;
    int i = 2 * p - (p & (j - 1));
    bool asc = ((i & s) == 0);
    unsigned long long a = g_key[i], b = g_key[i + j];
    cswap(a, b, asc);
    g_key[i] = a; g_key[i + j] = b;
}

// ---------------- 5: gather sorted boxes -----------------------------------
__global__ void k_gather() {
    int i = blockIdx.x * 256 + threadIdx.x;
    if (i >= PRE) return;
    unsigned idx = (unsigned)(g_key[i] & 0xFFFFFFFFull);
    float4 b = g_roi4[idx];
    g_sbox[i] = b;
    g_sarea[i] = __fmul_rn(__fadd_rn(__fsub_rn(b.w, b.y), 1.f),
                           __fadd_rn(__fsub_rn(b.z, b.x), 1.f));
    if (!g_valid[idx]) atomicOr(&g_rem0[i >> 6], 1ull << (i & 63));
}

// ---------------- 6: cooperative lazy-mask greedy NMS ----------------------
// groups of 256 candidates (4 chunks); 47 groups cover PRE=12000.
__global__ __launch_bounds__(256) void k_nms_coop(float* __restrict__ out) {
    cg::grid_group grid = cg::this_grid();
    __shared__ unsigned long long s_diag[256 * 4];
    __shared__ unsigned long long s_kw[4];
    __shared__ int s_pref[5];
    int t = threadIdx.x;
    int gtid = blockIdx.x * 256 + t;
    int gsz = gridDim.x * 256;

    for (int grp = 0; grp < 47; grp++) {
        int base = grp * 256;
        int n_local = min(256, PRE - base);
        int nk = *(volatile int*)&g_nkept;

        // Parallel A: candidates vs kept boxes
        for (int p = gtid; p < nk * 256; p += gsz) {
            int k = p >> 8, j = p & 255;
            if (j < n_local) {
                float4 c = g_sbox[base + j];
                float aj = g_sarea[base + j];
                if (iou_gt(g_kept_box[k], g_kept_area[k], c, aj))
                    atomicOr(&g_csup[j >> 6], 1ull << (j & 63));
            }
        }
        // Parallel B: within-group upper-tri masks
        for (int u = gtid; u < 1024; u += gsz) {
            int i = u >> 2, w = u & 3;
            unsigned long long bits = 0ull;
            if (i < n_local) {
                float4 bi = g_sbox[base + i];
                float aiv = g_sarea[base + i];
                int j0 = w * 64;
                int jlo = max(j0, i + 1), jhi = min(j0 + 64, n_local);
                for (int j = jlo; j < jhi; j++) {
                    if (iou_gt(bi, aiv, g_sbox[base + j], g_sarea[base + j]))
                        bits |= 1ull << (j - j0);
                }
            }
            g_gdiag[u] = bits;
        }
        grid.sync();

        if (blockIdx.x == 0) {
            for (int e = t; e < 1024; e += 256) s_diag[e] = g_gdiag[e];
            __syncthreads();
            if (t == 0) {
                unsigned long long sup[4], kw[4];
#pragma unroll
                for (int w = 0; w < 4; w++) {
                    sup[w] = g_csup[w] | g_rem0[grp * 4 + w];
                    int rem = n_local - w * 64;
                    if (rem <= 0) sup[w] = ~0ull;
                    else if (rem < 64) sup[w] |= ~((1ull << rem) - 1ull);
                    kw[w] = 0ull;
                }
#pragma unroll
                for (int w = 0; w < 4; w++) {
                    unsigned long long avail = ~sup[w];
                    while (avail) {
                        int i = __ffsll((long long)avail) - 1;
                        kw[w] |= 1ull << i;
                        int row = (w * 64 + i) * 4;
                        for (int w2 = w; w2 < 4; w2++) sup[w2] |= s_diag[row + w2];
                        unsigned long long lowmask = (i == 63) ? ~0ull : ((2ull << i) - 1ull);
                        avail = ~sup[w] & ~lowmask;
                    }
                }
                int pref = 0;
#pragma unroll
                for (int w = 0; w < 4; w++) {
                    s_kw[w] = kw[w];
                    s_pref[w] = pref;
                    pref += __popcll(kw[w]);
                }
                s_pref[4] = pref;
            }
            __syncthreads();
            {
                int w = t >> 6, b = t & 63;
                unsigned long long kwv = s_kw[w];
                if ((kwv >> b) & 1ull) {
                    int pos = nk + s_pref[w] + __popcll(kwv & ((1ull << b) - 1ull));
                    float4 bx = g_sbox[base + t];
                    if (pos < POST) {
                        out[OUT_ROIS + pos * 4 + 0] = bx.x;
                        out[OUT_ROIS + pos * 4 + 1] = bx.y;
                        out[OUT_ROIS + pos * 4 + 2] = bx.z;
                        out[OUT_ROIS + pos * 4 + 3] = bx.w;
                    }
                    g_kept_box[pos]  = bx;
                    g_kept_area[pos] = g_sarea[base + t];
                }
            }
            __syncthreads();
            if (t == 0) {
                int total = nk + s_pref[4];
                g_nkept = total;
                if (total >= POST) g_done = 1;
                g_csup[0] = 0ull; g_csup[1] = 0ull;
                g_csup[2] = 0ull; g_csup[3] = 0ull;
            }
        }
        grid.sync();
        if (*(volatile int*)&g_done) break;
    }
}

// ---------------- launch ----------------------------------------------------
extern "C" void kernel_launch(void* const* d_in, const int* in_sizes, int n_in,
                              void* d_out, int out_size) {
    const float* x   = (const float*)d_in[0];
    const float* c1w = (const float*)d_in[1];
    const float* c1b = (const float*)d_in[2];
    const float* rw  = (const float*)d_in[3];
    const float* rb  = (const float*)d_in[4];
    const float* cw  = (const float*)d_in[5];
    const float* cb  = (const float*)d_in[6];
    float* out = (float*)d_out;

    cudaFuncSetAttribute(k_conv, cudaFuncAttributeMaxDynamicSharedMemorySize, SMEM_CONV);

    k_wt<<<2304, 256>>>(c1w, out);
    k_conv<<<dim3(4, 52), 208, SMEM_CONV>>>(x, c1b);
    k_heads<<<676, 216>>>(rw, rb, cw, cb, out);

    k_sort_local_full<<<8, 1024>>>();
    k_sort_global<<<64, 256>>>(4096, 8192);
    k_sort_local_tail<<<8, 1024>>>(8192);
    k_sort_global<<<64, 256>>>(8192, 16384);
    k_sort_global<<<64, 256>>>(4096, 16384);
    k_sort_local_tail<<<8, 1024>>>(16384);
    k_sort_global<<<64, 256>>>(16384, 32768);
    k_sort_global<<<64, 256>>>(8192, 32768);
    k_sort_global<<<64, 256>>>(4096, 32768);
    k_sort_local_tail<<<8, 1024>>>(32768);

    k_gather<<<47, 256>>>();

    void* args[] = { (void*)&out };
    cudaLaunchCooperativeKernel((const void*)k_nms_coop, dim3(148), dim3(256),
                                args, 0, (cudaStream_t)0);
}